// round 10
// baseline (speedup 1.0000x reference)
#include <cuda_runtime.h>
#include <cuda_bf16.h>
#include <cstdint>

// VectorQuantize, GB300 (sm_103 base PTX: HMMA mma.sync path).
// Pinned-exact fp32 recipe (R4, rel_err==0):
//   dot  = single fp32 accumulator, FFMA, d ascending
//   dist = __fadd_rn(__fsub_rn(xsq, __fmul_rn(2.f, dot)), csq)
//   csq  = XLA warp row-reduce; argmin = first-min
// Phase1 v3 (R9, passed): persistent CTAs, 256 tokens/tile, bf16 HMMA filter.
// Rescue v4: parallel over (8-token group x 256-code quarter) jobs; cross-block
// argmin via atomicMin on packed (monotonic dist bits, code) u64 keys.

#define DDIM    256
#define KCODES  1024
#define NMAX    65536
#define RESCUE_THRESH 0.75f

__device__ float g_csq[KCODES];
__device__ float g_cbT[DDIM * KCODES];
__device__ float g_tokloss[NMAX];
__device__ int   g_bestidx[NMAX];
__device__ unsigned long long g_bestkey[NMAX];
__device__ int   g_rescue_list[NMAX];
__device__ int   g_rescue_cnt;
__device__ int   g_tile_ctr;
__device__ __nv_bfloat16 g_cbbf[KCODES * DDIM];

__device__ __forceinline__ uint32_t smem_u32(const void* p) {
    uint32_t a;
    asm("{ .reg .u64 t; cvta.to.shared.u64 t, %1; cvt.u32.u64 %0, t; }" : "=r"(a) : "l"(p));
    return a;
}
#define CP_ASYNC16(dst, src) \
    asm volatile("cp.async.cg.shared.global [%0], [%1], 16;" :: "r"(dst), "l"(src))
#define CP_COMMIT() asm volatile("cp.async.commit_group;" ::: "memory")
#define CP_WAIT0()  asm volatile("cp.async.wait_group 0;" ::: "memory")

__device__ __forceinline__ void ldmatrix_x4(uint32_t& r0, uint32_t& r1, uint32_t& r2,
                                            uint32_t& r3, uint32_t addr) {
    asm volatile("ldmatrix.sync.aligned.m8n8.x4.shared.b16 {%0,%1,%2,%3}, [%4];"
                 : "=r"(r0), "=r"(r1), "=r"(r2), "=r"(r3) : "r"(addr));
}
__device__ __forceinline__ void mma_bf16(float& c0, float& c1, float& c2, float& c3,
                                         uint32_t a0, uint32_t a1, uint32_t a2, uint32_t a3,
                                         uint32_t b0, uint32_t b1) {
    asm volatile("mma.sync.aligned.m16n8k16.row.col.f32.bf16.bf16.f32 "
                 "{%0,%1,%2,%3}, {%4,%5,%6,%7}, {%8,%9}, {%0,%1,%2,%3};"
                 : "+f"(c0), "+f"(c1), "+f"(c2), "+f"(c3)
                 : "r"(a0), "r"(a1), "r"(a2), "r"(a3), "r"(b0), "r"(b1));
}
// monotonic map: float bits -> u32 preserving value order (handles negatives)
__device__ __forceinline__ uint32_t fmono(float f) {
    uint32_t u = __float_as_uint(f);
    return u ^ (uint32_t)(((int32_t)u >> 31) | 0x80000000);
}

// ---------------- csq + cbT + cb-bf16 + counters reset ----------------
__global__ void csq_kernel(const float* __restrict__ cb) {
    if (blockIdx.x == 0 && threadIdx.x == 0) { g_rescue_cnt = 0; g_tile_ctr = 0; }
    const int warp = (blockIdx.x * blockDim.x + threadIdx.x) >> 5;
    const int lane = threadIdx.x & 31;
    if (warp >= KCODES) return;
    const float* row = cb + (size_t)warp * DDIM;
    float p = 0.f;
#pragma unroll
    for (int i = 0; i < 8; i++) {
        float v = row[lane + i * 32];
        g_cbT[(size_t)(lane + i * 32) * KCODES + warp] = v;
        g_cbbf[(size_t)warp * DDIM + lane + i * 32] = __float2bfloat16(v);
        p = __fadd_rn(p, __fmul_rn(v, v));
    }
#pragma unroll
    for (int off = 16; off > 0; off >>= 1)
        p = __fadd_rn(p, __shfl_down_sync(0xffffffffu, p, off));
    if (lane == 0) g_csq[warp] = p;
}

// ---------------- phase 1 v3 (unchanged from R9, passed) ----------------
#define PA_OFF   0
#define PB_OFF   131072
#define PC_OFF   196608
#define PTILE_OFF 197120
#define PT_TOTAL 197136

__global__ void __launch_bounds__(256, 1) vq_phase1(const float* __restrict__ x, int ntiles) {
    extern __shared__ char smem[];
    const uint32_t sb = smem_u32(smem);
    int* s_tile = reinterpret_cast<int*>(smem + PTILE_OFF);
    const int tid  = threadIdx.x;
    const int w    = tid >> 5;
    const int lane = tid & 31;

    const int q  = lane >> 2;
    const int qi = lane & 3;
    const int l7 = lane & 7;
    const int bnsel = lane >> 4;
    const int bkoff = (lane >> 3) & 1;
    const int arow  = w * 32 + (lane & 15);
    const uint32_t abase0 = sb + PA_OFF + arow * 512;
    const uint32_t abase1 = abase0 + 16 * 512;
    const int asw   = arow & 7;
    const int akoff = lane >> 4;

    for (;;) {
        if (tid == 0) s_tile[0] = atomicAdd(&g_tile_ctr, 1);
        __syncthreads();
        const int tile = s_tile[0];
        __syncthreads();
        if (tile >= ntiles) break;
        const int tokenBase = tile * 256;

        {
            const char* bsrc = reinterpret_cast<const char*>(g_cbbf);
            for (int u = tid; u < 2048; u += 256) {
                int row = u >> 5, c = u & 31;
                CP_ASYNC16(sb + PB_OFF + row * 512 + ((c ^ (row & 7)) << 4),
                           bsrc + row * 512 + (c << 4));
            }
            if (tid < 16)
                CP_ASYNC16(sb + PC_OFF + tid * 16,
                           reinterpret_cast<const char*>(g_csq) + tid * 16);
            CP_COMMIT();
        }
        {
            const float* xsrc = x + (size_t)tokenBase * DDIM;
            for (int u = tid; u < 8192; u += 256) {
                int row = u >> 5, c = u & 31;
                const float4* p = reinterpret_cast<const float4*>(xsrc + row * DDIM + c * 8);
                float4 v0 = p[0], v1 = p[1];
                __nv_bfloat162 b0 = __floats2bfloat162_rn(v0.x, v0.y);
                __nv_bfloat162 b1 = __floats2bfloat162_rn(v0.z, v0.w);
                __nv_bfloat162 b2 = __floats2bfloat162_rn(v1.x, v1.y);
                __nv_bfloat162 b3 = __floats2bfloat162_rn(v1.z, v1.w);
                uint4 wv;
                wv.x = *reinterpret_cast<uint32_t*>(&b0);
                wv.y = *reinterpret_cast<uint32_t*>(&b1);
                wv.z = *reinterpret_cast<uint32_t*>(&b2);
                wv.w = *reinterpret_cast<uint32_t*>(&b3);
                *reinterpret_cast<uint4*>(smem + PA_OFF + row * 512 + ((c ^ (row & 7)) << 4)) = wv;
            }
        }
        CP_WAIT0();
        __syncthreads();

        float bv0 = 3.4e38f, sv0 = 3.4e38f, bv1 = 3.4e38f, sv1 = 3.4e38f;
        float bv2 = 3.4e38f, sv2 = 3.4e38f, bv3 = 3.4e38f, sv3 = 3.4e38f;
        int bi0 = 0, bi1 = 0, bi2 = 0, bi3 = 0;

        for (int ch = 0; ch < 16; ch++) {
            const uint32_t Bcur = sb + PB_OFF + (ch & 1) * 32768;
            const float*   csqs = reinterpret_cast<const float*>(smem + PC_OFF + (ch & 1) * 256);

            if (ch + 1 < 16) {
                const uint32_t Bnxt = sb + PB_OFF + ((ch + 1) & 1) * 32768;
                const char* bsrc = reinterpret_cast<const char*>(
                    g_cbbf + (size_t)(ch + 1) * 64 * DDIM);
                for (int u = tid; u < 2048; u += 256) {
                    int row = u >> 5, c = u & 31;
                    CP_ASYNC16(Bnxt + row * 512 + ((c ^ (row & 7)) << 4),
                               bsrc + row * 512 + (c << 4));
                }
                if (tid < 16)
                    CP_ASYNC16(sb + PC_OFF + ((ch + 1) & 1) * 256 + tid * 16,
                               reinterpret_cast<const char*>(g_csq + (ch + 1) * 64) + tid * 16);
                CP_COMMIT();
            }

            float acc[2][8][4];
#pragma unroll
            for (int h = 0; h < 2; h++)
#pragma unroll
                for (int nt = 0; nt < 8; nt++)
#pragma unroll
                    for (int j = 0; j < 4; j++) acc[h][nt][j] = 0.f;

#pragma unroll
            for (int ks = 0; ks < 16; ks++) {
                const uint32_t aoff = (uint32_t)(((2 * ks + akoff) ^ asw) << 4);
                uint32_t a00, a01, a02, a03, a10, a11, a12, a13;
                ldmatrix_x4(a00, a01, a02, a03, abase0 + aoff);
                ldmatrix_x4(a10, a11, a12, a13, abase1 + aoff);
#pragma unroll
                for (int ntp = 0; ntp < 4; ntp++) {
                    uint32_t b0, b1, b2, b3;
                    int brow = (ntp * 2 + bnsel) * 8 + l7;
                    ldmatrix_x4(b0, b1, b2, b3,
                                Bcur + brow * 512 + (((2 * ks + bkoff) ^ l7) << 4));
                    mma_bf16(acc[0][ntp*2][0], acc[0][ntp*2][1], acc[0][ntp*2][2], acc[0][ntp*2][3],
                             a00, a01, a02, a03, b0, b1);
                    mma_bf16(acc[0][ntp*2+1][0], acc[0][ntp*2+1][1], acc[0][ntp*2+1][2], acc[0][ntp*2+1][3],
                             a00, a01, a02, a03, b2, b3);
                    mma_bf16(acc[1][ntp*2][0], acc[1][ntp*2][1], acc[1][ntp*2][2], acc[1][ntp*2][3],
                             a10, a11, a12, a13, b0, b1);
                    mma_bf16(acc[1][ntp*2+1][0], acc[1][ntp*2+1][1], acc[1][ntp*2+1][2], acc[1][ntp*2+1][3],
                             a10, a11, a12, a13, b2, b3);
                }
            }

#pragma unroll
            for (int nt = 0; nt < 8; nt++) {
                float2 cs = *reinterpret_cast<const float2*>(csqs + nt * 8 + 2 * qi);
                int code = ch * 64 + nt * 8 + 2 * qi;
                {
                    float d0 = __fmaf_rn(-2.0f, acc[0][nt][0], cs.x);
                    float d1 = __fmaf_rn(-2.0f, acc[0][nt][1], cs.y);
                    float d2 = __fmaf_rn(-2.0f, acc[0][nt][2], cs.x);
                    float d3 = __fmaf_rn(-2.0f, acc[0][nt][3], cs.y);
                    if (d0 < bv0) { sv0 = bv0; bv0 = d0; bi0 = code; } else if (d0 < sv0) sv0 = d0;
                    if (d1 < bv0) { sv0 = bv0; bv0 = d1; bi0 = code + 1; } else if (d1 < sv0) sv0 = d1;
                    if (d2 < bv1) { sv1 = bv1; bv1 = d2; bi1 = code; } else if (d2 < sv1) sv1 = d2;
                    if (d3 < bv1) { sv1 = bv1; bv1 = d3; bi1 = code + 1; } else if (d3 < sv1) sv1 = d3;
                }
                {
                    float d0 = __fmaf_rn(-2.0f, acc[1][nt][0], cs.x);
                    float d1 = __fmaf_rn(-2.0f, acc[1][nt][1], cs.y);
                    float d2 = __fmaf_rn(-2.0f, acc[1][nt][2], cs.x);
                    float d3 = __fmaf_rn(-2.0f, acc[1][nt][3], cs.y);
                    if (d0 < bv2) { sv2 = bv2; bv2 = d0; bi2 = code; } else if (d0 < sv2) sv2 = d0;
                    if (d1 < bv2) { sv2 = bv2; bv2 = d1; bi2 = code + 1; } else if (d1 < sv2) sv2 = d1;
                    if (d2 < bv3) { sv3 = bv3; bv3 = d2; bi3 = code; } else if (d2 < sv3) sv3 = d2;
                    if (d3 < bv3) { sv3 = bv3; bv3 = d3; bi3 = code + 1; } else if (d3 < sv3) sv3 = d3;
                }
            }

            CP_WAIT0();
            __syncthreads();
        }

#pragma unroll
        for (int m = 1; m <= 2; m <<= 1) {
            float ob, os; int oi;
            ob = __shfl_xor_sync(0xffffffffu, bv0, m); os = __shfl_xor_sync(0xffffffffu, sv0, m);
            oi = __shfl_xor_sync(0xffffffffu, bi0, m);
            if (ob < bv0 || (ob == bv0 && oi < bi0)) { sv0 = fminf(bv0, os); bv0 = ob; bi0 = oi; }
            else { sv0 = fminf(sv0, ob); }
            ob = __shfl_xor_sync(0xffffffffu, bv1, m); os = __shfl_xor_sync(0xffffffffu, sv1, m);
            oi = __shfl_xor_sync(0xffffffffu, bi1, m);
            if (ob < bv1 || (ob == bv1 && oi < bi1)) { sv1 = fminf(bv1, os); bv1 = ob; bi1 = oi; }
            else { sv1 = fminf(sv1, ob); }
            ob = __shfl_xor_sync(0xffffffffu, bv2, m); os = __shfl_xor_sync(0xffffffffu, sv2, m);
            oi = __shfl_xor_sync(0xffffffffu, bi2, m);
            if (ob < bv2 || (ob == bv2 && oi < bi2)) { sv2 = fminf(bv2, os); bv2 = ob; bi2 = oi; }
            else { sv2 = fminf(sv2, ob); }
            ob = __shfl_xor_sync(0xffffffffu, bv3, m); os = __shfl_xor_sync(0xffffffffu, sv3, m);
            oi = __shfl_xor_sync(0xffffffffu, bi3, m);
            if (ob < bv3 || (ob == bv3 && oi < bi3)) { sv3 = fminf(bv3, os); bv3 = ob; bi3 = oi; }
            else { sv3 = fminf(sv3, ob); }
        }

        if (qi == 0) {
            const int tb = tokenBase + w * 32;
            const int toks[4] = { tb + q, tb + q + 8, tb + 16 + q, tb + 24 + q };
            const float bvs[4] = { bv0, bv1, bv2, bv3 };
            const float svs[4] = { sv0, sv1, sv2, sv3 };
            const int   bis[4] = { bi0, bi1, bi2, bi3 };
#pragma unroll
            for (int s = 0; s < 4; s++) {
                if (svs[s] - bvs[s] < RESCUE_THRESH) {
                    g_bestidx[toks[s]] = -1;
                    g_bestkey[toks[s]] = ~0ull;
                    int p = atomicAdd(&g_rescue_cnt, 1);
                    if (p < NMAX) g_rescue_list[p] = toks[s];
                } else {
                    g_bestidx[toks[s]] = bis[s];
                }
            }
        }
        __syncthreads();
    }
}

// ---------------- exact rescue v4: parallel (token-group x code-quarter) ----------------
// block = 256 threads; job = 8 tokens x 256 codes (cq selects code quarter).
// thread = 1 code x 8 tokens; cross-block argmin via atomicMin on packed u64.
__global__ void __launch_bounds__(256) rescue_kernel(const float* __restrict__ x)
{
    __shared__ float xsT[DDIM * 8];     // [d][t]
    __shared__ float xqv[8];
    __shared__ int   stok[8];
    __shared__ unsigned long long wk[8][8];  // [warp][token]

    const int tid = threadIdx.x;
    const int warp = tid >> 5, lane = tid & 31;
    int cnt = g_rescue_cnt;
    if (cnt > NMAX) cnt = NMAX;

    const int cq = blockIdx.x & 3;
    const int k  = cq * 256 + tid;          // this thread's code
    const float csq = g_csq[k];
    const float* ccol = g_cbT + k;          // column k, stride KCODES

    const int rstride = gridDim.x >> 2;
    for (int r = blockIdx.x >> 2; r * 8 < cnt; r += rstride) {
        int nt = cnt - r * 8; if (nt > 8) nt = 8;
        __syncthreads();
        if (tid < nt) stok[tid] = g_rescue_list[r * 8 + tid];
        __syncthreads();
        for (int i = tid; i < nt * DDIM; i += 256) {
            int t = i >> 8, d = i & 255;
            xsT[d * 8 + t] = x[(size_t)stok[t] * DDIM + d];
        }
        if (nt < 8)
            for (int i = tid; i < (8 - nt) * DDIM; i += 256) {
                int t = nt + (i >> 8), d = i & 255;
                xsT[d * 8 + t] = 0.f;
            }
        __syncthreads();
        if (tid < nt) {   // pinned xsq: sequential d ascending, single accumulator
            float s = 0.f;
#pragma unroll 8
            for (int d = 0; d < DDIM; d++) {
                float v = xsT[d * 8 + tid];
                s += v * v;
            }
            xqv[tid] = s;
        }
        __syncthreads();

        float a[8];
#pragma unroll
        for (int t = 0; t < 8; t++) a[t] = 0.f;

#pragma unroll 4
        for (int d = 0; d < DDIM; d++) {
            float c = __ldg(ccol + (size_t)d * KCODES);
            float4 xv0 = *reinterpret_cast<const float4*>(&xsT[d * 8]);
            float4 xv1 = *reinterpret_cast<const float4*>(&xsT[d * 8 + 4]);
            a[0] = __fmaf_rn(xv0.x, c, a[0]);
            a[1] = __fmaf_rn(xv0.y, c, a[1]);
            a[2] = __fmaf_rn(xv0.z, c, a[2]);
            a[3] = __fmaf_rn(xv0.w, c, a[3]);
            a[4] = __fmaf_rn(xv1.x, c, a[4]);
            a[5] = __fmaf_rn(xv1.y, c, a[5]);
            a[6] = __fmaf_rn(xv1.z, c, a[6]);
            a[7] = __fmaf_rn(xv1.w, c, a[7]);
        }

        // pinned dist -> packed key -> warp min -> block min -> atomicMin
#pragma unroll
        for (int t = 0; t < 8; t++) {
            float dist = __fadd_rn(__fsub_rn(xqv[t], __fmul_rn(2.0f, a[t])), csq);
            unsigned long long key =
                ((unsigned long long)fmono(dist) << 32) | (unsigned)k;
#pragma unroll
            for (int off = 16; off > 0; off >>= 1) {
                unsigned long long o = __shfl_xor_sync(0xffffffffu, key, off);
                if (o < key) key = o;
            }
            if (lane == 0) wk[warp][t] = key;
        }
        __syncthreads();
        if (tid < nt) {
            unsigned long long key = wk[0][tid];
#pragma unroll
            for (int wv = 1; wv < 8; wv++) {
                unsigned long long o = wk[wv][tid];
                if (o < key) key = o;
            }
            atomicMin(&g_bestkey[stok[tid]], key);
        }
    }
}

// ---------------- gather + STE + loss ----------------
__global__ void __launch_bounds__(256) gather_kernel(
    const float* __restrict__ x, const float* __restrict__ cb,
    float* __restrict__ out, float* __restrict__ oidx)
{
    const int token = (blockIdx.x * 256 + threadIdx.x) >> 5;
    const int lane = threadIdx.x & 31;
    int k = g_bestidx[token];
    if (k < 0) k = (int)(unsigned)(g_bestkey[token] & 0xffffffffull);
    if (lane == 0 && oidx) oidx[token] = (float)k;
    const float4* xr = reinterpret_cast<const float4*>(x + (size_t)token * DDIM);
    const float4* qr = reinterpret_cast<const float4*>(cb + (size_t)k * DDIM);
    float4* orow = reinterpret_cast<float4*>(out + (size_t)token * DDIM);
    float s = 0.f;
#pragma unroll
    for (int h = 0; h < 2; h++) {
        int i = h * 32 + lane;
        float4 xv = xr[i], qv = qr[i];
        float4 o;
        o.x = xv.x + (qv.x - xv.x);
        o.y = xv.y + (qv.y - xv.y);
        o.z = xv.z + (qv.z - xv.z);
        o.w = xv.w + (qv.w - xv.w);
        orow[i] = o;
        float dx = xv.x - qv.x, dy = xv.y - qv.y, dz = xv.z - qv.z, dw = xv.w - qv.w;
        s += dx * dx + dy * dy + dz * dz + dw * dw;
    }
#pragma unroll
    for (int off = 16; off > 0; off >>= 1)
        s += __shfl_down_sync(0xffffffffu, s, off);
    if (lane == 0) g_tokloss[token] = s;
}

__global__ void loss_final(float* __restrict__ out_loss, float inv, int n) {
    __shared__ float red[1024];
    const int tid = threadIdx.x;
    float s = 0.f;
    for (int i = tid; i < n; i += 1024) s += g_tokloss[i];
    red[tid] = s;
    __syncthreads();
    for (int off = 512; off > 0; off >>= 1) {
        if (tid < off) red[tid] += red[tid + off];
        __syncthreads();
    }
    if (tid == 0) *out_loss = red[0] * inv;
}

extern "C" void kernel_launch(void* const* d_in, const int* in_sizes, int n_in,
                              void* d_out, int out_size)
{
    const float* x  = (const float*)d_in[0];
    const float* cb = (const float*)d_in[1];
    const long long n_elems = (long long)in_sizes[0];   // N * 256
    const int N = (int)(n_elems / DDIM);
    const int ntiles = N / 256;

    float* out   = (float*)d_out;
    float* oidx  = nullptr;
    float* oloss = nullptr;
    const long long need_idx = n_elems + N;
    if ((long long)out_size >= need_idx)      oidx  = out + n_elems;
    if ((long long)out_size >= need_idx + 1)  oloss = out + need_idx;
    else if ((long long)out_size == n_elems + 1) oloss = out + n_elems;

    cudaFuncSetAttribute(vq_phase1, cudaFuncAttributeMaxDynamicSharedMemorySize, PT_TOTAL);

    csq_kernel<<<(KCODES * 32 + 255) / 256, 256>>>(cb);
    vq_phase1<<<148, 256, PT_TOTAL>>>(x, ntiles);
    rescue_kernel<<<592, 256>>>(x);
    gather_kernel<<<N / 8, 256>>>(x, cb, out, oidx);
    if (oloss) loss_final<<<1, 1024>>>(oloss, 1.0f / ((float)N * (float)DDIM), N);
}

// round 11
// speedup vs baseline: 1.1684x; 1.1684x over previous
#include <cuda_runtime.h>
#include <cuda_bf16.h>
#include <cstdint>

// VectorQuantize, GB300 (sm_103 base PTX: HMMA mma.sync path).
// Pinned-exact fp32 recipe (R4, rel_err==0):
//   dot  = single fp32 accumulator, FFMA, d ascending
//   dist = __fadd_rn(__fsub_rn(xsq, __fmul_rn(2.f, dot)), csq)
//   csq  = XLA warp row-reduce; argmin = first-min
// Phase1 v3 (R9, passed): persistent CTAs, 256 tokens/tile, bf16 HMMA filter.
// Rescue v5: RT=4 tokens/block (short FFMA chains), threshold 0.6.

#define DDIM    256
#define KCODES  1024
#define NMAX    65536
#define RESCUE_THRESH 0.6f
#define RT      4

__device__ float g_csq[KCODES];
__device__ float g_cbT[DDIM * KCODES];
__device__ float g_tokloss[NMAX];
__device__ int   g_bestidx[NMAX];
__device__ int   g_rescue_list[NMAX];
__device__ int   g_rescue_cnt;
__device__ int   g_tile_ctr;
__device__ __nv_bfloat16 g_cbbf[KCODES * DDIM];

__device__ __forceinline__ uint32_t smem_u32(const void* p) {
    uint32_t a;
    asm("{ .reg .u64 t; cvta.to.shared.u64 t, %1; cvt.u32.u64 %0, t; }" : "=r"(a) : "l"(p));
    return a;
}
#define CP_ASYNC16(dst, src) \
    asm volatile("cp.async.cg.shared.global [%0], [%1], 16;" :: "r"(dst), "l"(src))
#define CP_COMMIT() asm volatile("cp.async.commit_group;" ::: "memory")
#define CP_WAIT0()  asm volatile("cp.async.wait_group 0;" ::: "memory")

__device__ __forceinline__ void ldmatrix_x4(uint32_t& r0, uint32_t& r1, uint32_t& r2,
                                            uint32_t& r3, uint32_t addr) {
    asm volatile("ldmatrix.sync.aligned.m8n8.x4.shared.b16 {%0,%1,%2,%3}, [%4];"
                 : "=r"(r0), "=r"(r1), "=r"(r2), "=r"(r3) : "r"(addr));
}
__device__ __forceinline__ void mma_bf16(float& c0, float& c1, float& c2, float& c3,
                                         uint32_t a0, uint32_t a1, uint32_t a2, uint32_t a3,
                                         uint32_t b0, uint32_t b1) {
    asm volatile("mma.sync.aligned.m16n8k16.row.col.f32.bf16.bf16.f32 "
                 "{%0,%1,%2,%3}, {%4,%5,%6,%7}, {%8,%9}, {%0,%1,%2,%3};"
                 : "+f"(c0), "+f"(c1), "+f"(c2), "+f"(c3)
                 : "r"(a0), "r"(a1), "r"(a2), "r"(a3), "r"(b0), "r"(b1));
}

// ---------------- csq + cbT + cb-bf16 + counters reset ----------------
__global__ void csq_kernel(const float* __restrict__ cb) {
    if (blockIdx.x == 0 && threadIdx.x == 0) { g_rescue_cnt = 0; g_tile_ctr = 0; }
    const int warp = (blockIdx.x * blockDim.x + threadIdx.x) >> 5;
    const int lane = threadIdx.x & 31;
    if (warp >= KCODES) return;
    const float* row = cb + (size_t)warp * DDIM;
    float p = 0.f;
#pragma unroll
    for (int i = 0; i < 8; i++) {
        float v = row[lane + i * 32];
        g_cbT[(size_t)(lane + i * 32) * KCODES + warp] = v;
        g_cbbf[(size_t)warp * DDIM + lane + i * 32] = __float2bfloat16(v);
        p = __fadd_rn(p, __fmul_rn(v, v));
    }
#pragma unroll
    for (int off = 16; off > 0; off >>= 1)
        p = __fadd_rn(p, __shfl_down_sync(0xffffffffu, p, off));
    if (lane == 0) g_csq[warp] = p;
}

// ---------------- phase 1 v3 (unchanged from R9, passed) ----------------
#define PA_OFF   0
#define PB_OFF   131072
#define PC_OFF   196608
#define PTILE_OFF 197120
#define PT_TOTAL 197136

__global__ void __launch_bounds__(256, 1) vq_phase1(const float* __restrict__ x, int ntiles) {
    extern __shared__ char smem[];
    const uint32_t sb = smem_u32(smem);
    int* s_tile = reinterpret_cast<int*>(smem + PTILE_OFF);
    const int tid  = threadIdx.x;
    const int w    = tid >> 5;
    const int lane = tid & 31;

    const int q  = lane >> 2;
    const int qi = lane & 3;
    const int l7 = lane & 7;
    const int bnsel = lane >> 4;
    const int bkoff = (lane >> 3) & 1;
    const int arow  = w * 32 + (lane & 15);
    const uint32_t abase0 = sb + PA_OFF + arow * 512;
    const uint32_t abase1 = abase0 + 16 * 512;
    const int asw   = arow & 7;
    const int akoff = lane >> 4;

    for (;;) {
        if (tid == 0) s_tile[0] = atomicAdd(&g_tile_ctr, 1);
        __syncthreads();
        const int tile = s_tile[0];
        __syncthreads();
        if (tile >= ntiles) break;
        const int tokenBase = tile * 256;

        {
            const char* bsrc = reinterpret_cast<const char*>(g_cbbf);
            for (int u = tid; u < 2048; u += 256) {
                int row = u >> 5, c = u & 31;
                CP_ASYNC16(sb + PB_OFF + row * 512 + ((c ^ (row & 7)) << 4),
                           bsrc + row * 512 + (c << 4));
            }
            if (tid < 16)
                CP_ASYNC16(sb + PC_OFF + tid * 16,
                           reinterpret_cast<const char*>(g_csq) + tid * 16);
            CP_COMMIT();
        }
        {
            const float* xsrc = x + (size_t)tokenBase * DDIM;
            for (int u = tid; u < 8192; u += 256) {
                int row = u >> 5, c = u & 31;
                const float4* p = reinterpret_cast<const float4*>(xsrc + row * DDIM + c * 8);
                float4 v0 = p[0], v1 = p[1];
                __nv_bfloat162 b0 = __floats2bfloat162_rn(v0.x, v0.y);
                __nv_bfloat162 b1 = __floats2bfloat162_rn(v0.z, v0.w);
                __nv_bfloat162 b2 = __floats2bfloat162_rn(v1.x, v1.y);
                __nv_bfloat162 b3 = __floats2bfloat162_rn(v1.z, v1.w);
                uint4 wv;
                wv.x = *reinterpret_cast<uint32_t*>(&b0);
                wv.y = *reinterpret_cast<uint32_t*>(&b1);
                wv.z = *reinterpret_cast<uint32_t*>(&b2);
                wv.w = *reinterpret_cast<uint32_t*>(&b3);
                *reinterpret_cast<uint4*>(smem + PA_OFF + row * 512 + ((c ^ (row & 7)) << 4)) = wv;
            }
        }
        CP_WAIT0();
        __syncthreads();

        float bv0 = 3.4e38f, sv0 = 3.4e38f, bv1 = 3.4e38f, sv1 = 3.4e38f;
        float bv2 = 3.4e38f, sv2 = 3.4e38f, bv3 = 3.4e38f, sv3 = 3.4e38f;
        int bi0 = 0, bi1 = 0, bi2 = 0, bi3 = 0;

        for (int ch = 0; ch < 16; ch++) {
            const uint32_t Bcur = sb + PB_OFF + (ch & 1) * 32768;
            const float*   csqs = reinterpret_cast<const float*>(smem + PC_OFF + (ch & 1) * 256);

            if (ch + 1 < 16) {
                const uint32_t Bnxt = sb + PB_OFF + ((ch + 1) & 1) * 32768;
                const char* bsrc = reinterpret_cast<const char*>(
                    g_cbbf + (size_t)(ch + 1) * 64 * DDIM);
                for (int u = tid; u < 2048; u += 256) {
                    int row = u >> 5, c = u & 31;
                    CP_ASYNC16(Bnxt + row * 512 + ((c ^ (row & 7)) << 4),
                               bsrc + row * 512 + (c << 4));
                }
                if (tid < 16)
                    CP_ASYNC16(sb + PC_OFF + ((ch + 1) & 1) * 256 + tid * 16,
                               reinterpret_cast<const char*>(g_csq + (ch + 1) * 64) + tid * 16);
                CP_COMMIT();
            }

            float acc[2][8][4];
#pragma unroll
            for (int h = 0; h < 2; h++)
#pragma unroll
                for (int nt = 0; nt < 8; nt++)
#pragma unroll
                    for (int j = 0; j < 4; j++) acc[h][nt][j] = 0.f;

#pragma unroll
            for (int ks = 0; ks < 16; ks++) {
                const uint32_t aoff = (uint32_t)(((2 * ks + akoff) ^ asw) << 4);
                uint32_t a00, a01, a02, a03, a10, a11, a12, a13;
                ldmatrix_x4(a00, a01, a02, a03, abase0 + aoff);
                ldmatrix_x4(a10, a11, a12, a13, abase1 + aoff);
#pragma unroll
                for (int ntp = 0; ntp < 4; ntp++) {
                    uint32_t b0, b1, b2, b3;
                    int brow = (ntp * 2 + bnsel) * 8 + l7;
                    ldmatrix_x4(b0, b1, b2, b3,
                                Bcur + brow * 512 + (((2 * ks + bkoff) ^ l7) << 4));
                    mma_bf16(acc[0][ntp*2][0], acc[0][ntp*2][1], acc[0][ntp*2][2], acc[0][ntp*2][3],
                             a00, a01, a02, a03, b0, b1);
                    mma_bf16(acc[0][ntp*2+1][0], acc[0][ntp*2+1][1], acc[0][ntp*2+1][2], acc[0][ntp*2+1][3],
                             a00, a01, a02, a03, b2, b3);
                    mma_bf16(acc[1][ntp*2][0], acc[1][ntp*2][1], acc[1][ntp*2][2], acc[1][ntp*2][3],
                             a10, a11, a12, a13, b0, b1);
                    mma_bf16(acc[1][ntp*2+1][0], acc[1][ntp*2+1][1], acc[1][ntp*2+1][2], acc[1][ntp*2+1][3],
                             a10, a11, a12, a13, b2, b3);
                }
            }

#pragma unroll
            for (int nt = 0; nt < 8; nt++) {
                float2 cs = *reinterpret_cast<const float2*>(csqs + nt * 8 + 2 * qi);
                int code = ch * 64 + nt * 8 + 2 * qi;
                {
                    float d0 = __fmaf_rn(-2.0f, acc[0][nt][0], cs.x);
                    float d1 = __fmaf_rn(-2.0f, acc[0][nt][1], cs.y);
                    float d2 = __fmaf_rn(-2.0f, acc[0][nt][2], cs.x);
                    float d3 = __fmaf_rn(-2.0f, acc[0][nt][3], cs.y);
                    if (d0 < bv0) { sv0 = bv0; bv0 = d0; bi0 = code; } else if (d0 < sv0) sv0 = d0;
                    if (d1 < bv0) { sv0 = bv0; bv0 = d1; bi0 = code + 1; } else if (d1 < sv0) sv0 = d1;
                    if (d2 < bv1) { sv1 = bv1; bv1 = d2; bi1 = code; } else if (d2 < sv1) sv1 = d2;
                    if (d3 < bv1) { sv1 = bv1; bv1 = d3; bi1 = code + 1; } else if (d3 < sv1) sv1 = d3;
                }
                {
                    float d0 = __fmaf_rn(-2.0f, acc[1][nt][0], cs.x);
                    float d1 = __fmaf_rn(-2.0f, acc[1][nt][1], cs.y);
                    float d2 = __fmaf_rn(-2.0f, acc[1][nt][2], cs.x);
                    float d3 = __fmaf_rn(-2.0f, acc[1][nt][3], cs.y);
                    if (d0 < bv2) { sv2 = bv2; bv2 = d0; bi2 = code; } else if (d0 < sv2) sv2 = d0;
                    if (d1 < bv2) { sv2 = bv2; bv2 = d1; bi2 = code + 1; } else if (d1 < sv2) sv2 = d1;
                    if (d2 < bv3) { sv3 = bv3; bv3 = d2; bi3 = code; } else if (d2 < sv3) sv3 = d2;
                    if (d3 < bv3) { sv3 = bv3; bv3 = d3; bi3 = code + 1; } else if (d3 < sv3) sv3 = d3;
                }
            }

            CP_WAIT0();
            __syncthreads();
        }

#pragma unroll
        for (int m = 1; m <= 2; m <<= 1) {
            float ob, os; int oi;
            ob = __shfl_xor_sync(0xffffffffu, bv0, m); os = __shfl_xor_sync(0xffffffffu, sv0, m);
            oi = __shfl_xor_sync(0xffffffffu, bi0, m);
            if (ob < bv0 || (ob == bv0 && oi < bi0)) { sv0 = fminf(bv0, os); bv0 = ob; bi0 = oi; }
            else { sv0 = fminf(sv0, ob); }
            ob = __shfl_xor_sync(0xffffffffu, bv1, m); os = __shfl_xor_sync(0xffffffffu, sv1, m);
            oi = __shfl_xor_sync(0xffffffffu, bi1, m);
            if (ob < bv1 || (ob == bv1 && oi < bi1)) { sv1 = fminf(bv1, os); bv1 = ob; bi1 = oi; }
            else { sv1 = fminf(sv1, ob); }
            ob = __shfl_xor_sync(0xffffffffu, bv2, m); os = __shfl_xor_sync(0xffffffffu, sv2, m);
            oi = __shfl_xor_sync(0xffffffffu, bi2, m);
            if (ob < bv2 || (ob == bv2 && oi < bi2)) { sv2 = fminf(bv2, os); bv2 = ob; bi2 = oi; }
            else { sv2 = fminf(sv2, ob); }
            ob = __shfl_xor_sync(0xffffffffu, bv3, m); os = __shfl_xor_sync(0xffffffffu, sv3, m);
            oi = __shfl_xor_sync(0xffffffffu, bi3, m);
            if (ob < bv3 || (ob == bv3 && oi < bi3)) { sv3 = fminf(bv3, os); bv3 = ob; bi3 = oi; }
            else { sv3 = fminf(sv3, ob); }
        }

        if (qi == 0) {
            const int tb = tokenBase + w * 32;
            const int toks[4] = { tb + q, tb + q + 8, tb + 16 + q, tb + 24 + q };
            const float bvs[4] = { bv0, bv1, bv2, bv3 };
            const float svs[4] = { sv0, sv1, sv2, sv3 };
            const int   bis[4] = { bi0, bi1, bi2, bi3 };
#pragma unroll
            for (int s = 0; s < 4; s++) {
                g_bestidx[toks[s]] = bis[s];
                if (svs[s] - bvs[s] < RESCUE_THRESH) {
                    int p = atomicAdd(&g_rescue_cnt, 1);
                    if (p < NMAX) g_rescue_list[p] = toks[s];
                }
            }
        }
        __syncthreads();
    }
}

// ---------------- exact rescue v5: RT=4 tokens/block, broadcast float4 x ----------------
__global__ void __launch_bounds__(256) rescue_kernel(const float* __restrict__ x)
{
    __shared__ float xsT[DDIM * RT];              // [d][t], stride 4 (aligned float4)
    __shared__ float xqv[RT];
    __shared__ int   stok[RT];
    __shared__ unsigned long long wkeys[8][RT];

    const int tid = threadIdx.x;
    const int warp = tid >> 5, lane = tid & 31;
    int cnt = g_rescue_cnt;
    if (cnt > NMAX) cnt = NMAX;

    const float4 csqv = *reinterpret_cast<const float4*>(g_csq + tid * 4);
    const float4* ct = reinterpret_cast<const float4*>(g_cbT) + tid;

    for (int base = blockIdx.x * RT; base < cnt; base += gridDim.x * RT) {
        int nt = cnt - base; if (nt > RT) nt = RT;
        __syncthreads();
        if (tid < nt) stok[tid] = g_rescue_list[base + tid];
        __syncthreads();
        for (int i = tid; i < nt * DDIM; i += 256) {
            int t = i >> 8, d = i & 255;
            xsT[d * RT + t] = x[(size_t)stok[t] * DDIM + d];
        }
        if (nt < RT)
            for (int i = tid; i < (RT - nt) * DDIM; i += 256) {
                int t = nt + (i >> 8), d = i & 255;
                xsT[d * RT + t] = 0.f;
            }
        __syncthreads();
        if (tid < nt) {   // pinned xsq: sequential d ascending, single accumulator
            float s = 0.f;
#pragma unroll 8
            for (int d = 0; d < DDIM; d++) {
                float v = xsT[d * RT + tid];
                s += v * v;
            }
            xqv[tid] = s;
        }
        __syncthreads();

        float a0[RT], a1[RT], a2[RT], a3[RT];
#pragma unroll
        for (int t = 0; t < RT; t++) { a0[t] = 0.f; a1[t] = 0.f; a2[t] = 0.f; a3[t] = 0.f; }

#pragma unroll 4
        for (int d = 0; d < DDIM; d++) {
            float4 c = __ldg(ct + d * (KCODES / 4));
            float4 xv = *reinterpret_cast<const float4*>(&xsT[d * RT]);   // broadcast
            const float xvv[RT] = { xv.x, xv.y, xv.z, xv.w };
#pragma unroll
            for (int t = 0; t < RT; t++) {
                a0[t] = __fmaf_rn(xvv[t], c.x, a0[t]);
                a1[t] = __fmaf_rn(xvv[t], c.y, a1[t]);
                a2[t] = __fmaf_rn(xvv[t], c.z, a2[t]);
                a3[t] = __fmaf_rn(xvv[t], c.w, a3[t]);
            }
        }

        // pinned dist; pack (dist bits, code) -> u64; dist>0 so bit order = value order
#pragma unroll
        for (int t = 0; t < RT; t++) {
            float q = xqv[t];
            float d0 = __fadd_rn(__fsub_rn(q, __fmul_rn(2.0f, a0[t])), csqv.x);
            float d1 = __fadd_rn(__fsub_rn(q, __fmul_rn(2.0f, a1[t])), csqv.y);
            float d2 = __fadd_rn(__fsub_rn(q, __fmul_rn(2.0f, a2[t])), csqv.z);
            float d3 = __fadd_rn(__fsub_rn(q, __fmul_rn(2.0f, a3[t])), csqv.w);
            unsigned long long k0 = ((unsigned long long)__float_as_uint(d0) << 32) | (unsigned)(tid * 4);
            unsigned long long k1 = ((unsigned long long)__float_as_uint(d1) << 32) | (unsigned)(tid * 4 + 1);
            unsigned long long k2 = ((unsigned long long)__float_as_uint(d2) << 32) | (unsigned)(tid * 4 + 2);
            unsigned long long k3 = ((unsigned long long)__float_as_uint(d3) << 32) | (unsigned)(tid * 4 + 3);
            unsigned long long k = k0;
            if (k1 < k) k = k1;
            if (k2 < k) k = k2;
            if (k3 < k) k = k3;
#pragma unroll
            for (int off = 16; off > 0; off >>= 1) {
                unsigned long long o = __shfl_xor_sync(0xffffffffu, k, off);
                if (o < k) k = o;
            }
            if (lane == 0) wkeys[warp][t] = k;
        }
        __syncthreads();
        if (tid < nt) {
            unsigned long long k = wkeys[0][tid];
#pragma unroll
            for (int wv = 1; wv < 8; wv++) {
                unsigned long long o = wkeys[wv][tid];
                if (o < k) k = o;
            }
            g_bestidx[stok[tid]] = (int)(k & 0xffffffffu);
        }
    }
}

// ---------------- gather + STE + loss ----------------
__global__ void __launch_bounds__(256) gather_kernel(
    const float* __restrict__ x, const float* __restrict__ cb,
    float* __restrict__ out, float* __restrict__ oidx)
{
    const int token = (blockIdx.x * 256 + threadIdx.x) >> 5;
    const int lane = threadIdx.x & 31;
    const int k = g_bestidx[token];
    if (lane == 0 && oidx) oidx[token] = (float)k;
    const float4* xr = reinterpret_cast<const float4*>(x + (size_t)token * DDIM);
    const float4* qr = reinterpret_cast<const float4*>(cb + (size_t)k * DDIM);
    float4* orow = reinterpret_cast<float4*>(out + (size_t)token * DDIM);
    float s = 0.f;
#pragma unroll
    for (int h = 0; h < 2; h++) {
        int i = h * 32 + lane;
        float4 xv = xr[i], qv = qr[i];
        float4 o;
        o.x = xv.x + (qv.x - xv.x);
        o.y = xv.y + (qv.y - xv.y);
        o.z = xv.z + (qv.z - xv.z);
        o.w = xv.w + (qv.w - xv.w);
        orow[i] = o;
        float dx = xv.x - qv.x, dy = xv.y - qv.y, dz = xv.z - qv.z, dw = xv.w - qv.w;
        s += dx * dx + dy * dy + dz * dz + dw * dw;
    }
#pragma unroll
    for (int off = 16; off > 0; off >>= 1)
        s += __shfl_down_sync(0xffffffffu, s, off);
    if (lane == 0) g_tokloss[token] = s;
}

__global__ void loss_final(float* __restrict__ out_loss, float inv, int n) {
    __shared__ float red[1024];
    const int tid = threadIdx.x;
    float s = 0.f;
    for (int i = tid; i < n; i += 1024) s += g_tokloss[i];
    red[tid] = s;
    __syncthreads();
    for (int off = 512; off > 0; off >>= 1) {
        if (tid < off) red[tid] += red[tid + off];
        __syncthreads();
    }
    if (tid == 0) *out_loss = red[0] * inv;
}

extern "C" void kernel_launch(void* const* d_in, const int* in_sizes, int n_in,
                              void* d_out, int out_size)
{
    const float* x  = (const float*)d_in[0];
    const float* cb = (const float*)d_in[1];
    const long long n_elems = (long long)in_sizes[0];   // N * 256
    const int N = (int)(n_elems / DDIM);
    const int ntiles = N / 256;

    float* out   = (float*)d_out;
    float* oidx  = nullptr;
    float* oloss = nullptr;
    const long long need_idx = n_elems + N;
    if ((long long)out_size >= need_idx)      oidx  = out + n_elems;
    if ((long long)out_size >= need_idx + 1)  oloss = out + need_idx;
    else if ((long long)out_size == n_elems + 1) oloss = out + n_elems;

    cudaFuncSetAttribute(vq_phase1, cudaFuncAttributeMaxDynamicSharedMemorySize, PT_TOTAL);

    csq_kernel<<<(KCODES * 32 + 255) / 256, 256>>>(cb);
    vq_phase1<<<148, 256, PT_TOTAL>>>(x, ntiles);
    rescue_kernel<<<592, 256>>>(x);
    gather_kernel<<<N / 8, 256>>>(x, cb, out, oidx);
    if (oloss) loss_final<<<1, 1024>>>(oloss, 1.0f / ((float)N * (float)DDIM), N);
}